// round 9
// baseline (speedup 1.0000x reference)
#include <cuda_runtime.h>
#include <cuda_bf16.h>
#include <cstddef>

#define DK 64
#define TPB 160             // 5 warps
#define ITEM_BLOCKS 444
#define B_MAX 4096

// Scratch (no cudaMalloc allowed)
__device__ float g_G1[DK * DK];     // item_W^T item_W   (atomic)
__device__ float g_G2[DK * DK];     // u_emb^T u_emb     (atomic)
__device__ float g_posp[B_MAX];     // per-row pos-loss partials

// ---------------------------------------------------------------------------
// One kernel, three block roles:
//   [0, ITEM_BLOCKS)               : item Gram (upper-tri 4x4 tiles, 136 thr)
//   [ITEM_BLOCKS, ITEM_BLOCKS+nG2) : user Gram (64 gathered rows per block)
//   [ITEM_BLOCKS+nG2, ...+B)       : pos_data_loss, one block per batch row
__global__ void __launch_bounds__(TPB, 10)
k_fused(const int* __restrict__ uids,
        const int* __restrict__ pos_iids,
        const float* __restrict__ userW,
        const float* __restrict__ itemW,
        const float* __restrict__ h,
        int B, int L, int PAD, int R, int nG2) {
    __shared__ float sm[64 * DK];       // 16 KB tile / wu scratch
    __shared__ float wsum[TPB / 32];
    const int tid = threadIdx.x;
    const int bid = blockIdx.x;

    if (bid < ITEM_BLOCKS + nG2) {
        // ------------------ Gram path (item or user) ------------------
        const bool isItem = bid < ITEM_BLOCKS;
        int ti = 0, tj = 0;
        const bool active = tid < 136;
        if (active) {                       // upper-tri tile map
            int k = tid, t = 0;
            while (k >= 16 - t) { k -= 16 - t; t++; }
            ti = t; tj = t + k;
        }
        float acc[4][4];
#pragma unroll
        for (int a = 0; a < 4; a++)
#pragma unroll
            for (int b = 0; b < 4; b++) acc[a][b] = 0.f;

        if (isItem) {
            const int n_tiles = (R + 63) / 64;
            for (int t = bid; t < n_tiles; t += ITEM_BLOCKS) {
                const int row0  = t * 64;
                const int valid = min(64, R - row0);
                __syncthreads();
                const float4* src = (const float4*)(itemW + (size_t)row0 * DK);
                float4* dst = (float4*)sm;
                for (int i = tid; i < valid * (DK / 4); i += TPB) dst[i] = src[i];
                __syncthreads();
                if (active) {
                    if (valid == 64) {
#pragma unroll 4
                        for (int r = 0; r < 64; r++) {
                            float4 vi = *(const float4*)&sm[r * DK + ti * 4];
                            float4 vj = *(const float4*)&sm[r * DK + tj * 4];
                            float ai[4] = {vi.x, vi.y, vi.z, vi.w};
                            float aj[4] = {vj.x, vj.y, vj.z, vj.w};
#pragma unroll
                            for (int a = 0; a < 4; a++)
#pragma unroll
                                for (int b = 0; b < 4; b++) acc[a][b] += ai[a] * aj[b];
                        }
                    } else {
                        for (int r = 0; r < valid; r++) {
                            float4 vi = *(const float4*)&sm[r * DK + ti * 4];
                            float4 vj = *(const float4*)&sm[r * DK + tj * 4];
                            float ai[4] = {vi.x, vi.y, vi.z, vi.w};
                            float aj[4] = {vj.x, vj.y, vj.z, vj.w};
#pragma unroll
                            for (int a = 0; a < 4; a++)
#pragma unroll
                                for (int b = 0; b < 4; b++) acc[a][b] += ai[a] * aj[b];
                        }
                    }
                }
            }
        } else {
            const int base = (bid - ITEM_BLOCKS) * 64;
            for (int i = tid; i < 64 * DK; i += TPB) {
                int u = base + (i >> 6);
                sm[i] = (u < B) ? userW[(size_t)uids[u] * DK + (i & 63)] : 0.f;
            }
            __syncthreads();
            if (active) {
#pragma unroll 4
                for (int r = 0; r < 64; r++) {
                    float4 vi = *(const float4*)&sm[r * DK + ti * 4];
                    float4 vj = *(const float4*)&sm[r * DK + tj * 4];
                    float ai[4] = {vi.x, vi.y, vi.z, vi.w};
                    float aj[4] = {vj.x, vj.y, vj.z, vj.w};
#pragma unroll
                    for (int a = 0; a < 4; a++)
#pragma unroll
                        for (int b = 0; b < 4; b++) acc[a][b] += ai[a] * aj[b];
                }
            }
        }
        if (active) {
            float* G = isItem ? g_G1 : g_G2;
#pragma unroll
            for (int a = 0; a < 4; a++)
#pragma unroll
                for (int b = 0; b < 4; b++)
                    atomicAdd(&G[(ti * 4 + a) * DK + tj * 4 + b], acc[a][b]);
            if (ti != tj) {
#pragma unroll
                for (int a = 0; a < 4; a++)
#pragma unroll
                    for (int b = 0; b < 4; b++)
                        atomicAdd(&G[(tj * 4 + b) * DK + ti * 4 + a], acc[a][b]);
            }
        }
    } else {
        // ------------------ hpq: one block per batch row b ------------------
        const int b    = bid - ITEM_BLOCKS - nG2;
        const int lane = tid & 31, w = tid >> 5;
        const int sub  = lane & 7, grp = lane >> 3;

        // wu = userW[uids[b]] * h, computed in-block
        if (tid < DK / 4) {
            float4 hu = ((const float4*)h)[tid];
            float4 uu = ((const float4*)(userW + (size_t)uids[b] * DK))[tid];
            float4 r;
            r.x = hu.x * uu.x; r.y = hu.y * uu.y;
            r.z = hu.z * uu.z; r.w = hu.w * uu.w;
            ((float4*)sm)[tid] = r;
        }
        __syncthreads();

        const float4 w0 = ((const float4*)sm)[sub];        // bytes [0,128)
        const float4 w1 = ((const float4*)sm)[sub + 8];    // bytes [128,256)
        const int* ids = pos_iids + (size_t)b * L;

        float loss = 0.f;
        const int per_step = (TPB / 32) * 16;              // 80 items/step
        const int nsteps = (L + per_step - 1) / per_step;  // 3 for L=200
        for (int s = 0; s < nsteps; s++) {
            const int l0 = s * per_step + (w * 4 + grp) * 4;
            int4 ii;
            if (l0 + 3 < L) {
                ii = *(const int4*)&ids[l0];               // 16B-aligned
            } else {
                ii.x = (l0     < L) ? ids[l0]     : PAD;
                ii.y = (l0 + 1 < L) ? ids[l0 + 1] : PAD;
                ii.z = (l0 + 2 < L) ? ids[l0 + 2] : PAD;
                ii.w = (l0 + 3 < L) ? ids[l0 + 3] : PAD;
            }
            const int iid[4] = {ii.x, ii.y, ii.z, ii.w};
            float4 va[4], vb[4];
#pragma unroll
            for (int t = 0; t < 4; t++) {
                const float4* row = (const float4*)(itemW + (size_t)iid[t] * DK);
                va[t] = row[sub];
                vb[t] = row[sub + 8];
            }
            float d[4];
#pragma unroll
            for (int t = 0; t < 4; t++)
                d[t] = va[t].x * w0.x + va[t].y * w0.y + va[t].z * w0.z + va[t].w * w0.w
                     + vb[t].x * w1.x + vb[t].y * w1.y + vb[t].z * w1.z + vb[t].w * w1.w;
#pragma unroll
            for (int off = 4; off; off >>= 1)
#pragma unroll
                for (int t = 0; t < 4; t++)
                    d[t] += __shfl_xor_sync(0xffffffffu, d[t], off);
            if (sub == 0) {
#pragma unroll
                for (int t = 0; t < 4; t++)
                    if (l0 + t < L && iid[t] != PAD)
                        loss += 0.9f * d[t] * d[t] - 2.0f * d[t];
            }
        }
#pragma unroll
        for (int off = 16; off; off >>= 1)
            loss += __shfl_xor_sync(0xffffffffu, loss, off);
        if (lane == 0) wsum[w] = loss;
        __syncthreads();
        if (tid == 0) {
            float s = 0.f;
#pragma unroll
            for (int k = 0; k < TPB / 32; k++) s += wsum[k];
            g_posp[b] = s;                                 // no atomic
        }
    }
}

// ---------------------------------------------------------------------------
__global__ void k_combine(const float* __restrict__ h, float* __restrict__ out,
                          int B) {
    __shared__ double red[256];
    const int tid = threadIdx.x;
    double s = 0.0;
    for (int e = tid; e < DK * DK; e += 256)
        s += (double)g_G1[e] * (double)g_G2[e] *
             (double)(h[e >> 6] * h[e & 63]);
    s *= 0.1;
    for (int i = tid; i < B; i += 256)
        s += (double)g_posp[i];
    red[tid] = s;
    __syncthreads();
    for (int k = 128; k; k >>= 1) {
        if (tid < k) red[tid] += red[tid + k];
        __syncthreads();
    }
    if (tid == 0) out[0] = (float)red[0];
}

// ---------------------------------------------------------------------------
extern "C" void kernel_launch(void* const* d_in, const int* in_sizes, int n_in,
                              void* d_out, int out_size) {
    const int*   uids     = (const int*)d_in[0];
    const int*   pos_iids = (const int*)d_in[1];
    const float* user_W   = (const float*)d_in[2];
    const float* item_W   = (const float*)d_in[3];
    const float* h        = (const float*)d_in[4];
    float* out = (float*)d_out;

    const int B   = in_sizes[0];          // 4096
    const int L   = in_sizes[1] / B;      // 200
    const int R   = in_sizes[3] / DK;     // 100001 item rows
    const int PAD = R - 1;                // padding item id
    const int nG2 = (B + 63) / 64;        // user-gram blocks

    void *pG1 = nullptr, *pG2 = nullptr;
    cudaGetSymbolAddress(&pG1, g_G1);
    cudaGetSymbolAddress(&pG2, g_G2);
    cudaMemsetAsync(pG1, 0, DK * DK * sizeof(float));
    cudaMemsetAsync(pG2, 0, DK * DK * sizeof(float));

    k_fused<<<ITEM_BLOCKS + nG2 + B, TPB>>>(uids, pos_iids, user_W, item_W, h,
                                            B, L, PAD, R, nG2);
    k_combine<<<1, 256>>>(h, out, B);
}

// round 14
// speedup vs baseline: 1.5748x; 1.5748x over previous
#include <cuda_runtime.h>
#include <cuda_bf16.h>
#include <cstddef>

#define DK 64
#define TPB 160             // 5 warps
#define ITEM_BLOCKS 444
#define B_MAX 4096

// Scratch (no cudaMalloc allowed)
__device__ float g_G1[DK * DK];     // item_W^T item_W   (atomic)
__device__ float g_G2[DK * DK];     // u_emb^T u_emb     (atomic)
__device__ float g_posp[B_MAX];     // per-row pos-loss partials

// ---------------------------------------------------------------------------
// One kernel, three block roles:
//   [0, ITEM_BLOCKS)               : item Gram (upper-tri 4x4 tiles, 136 thr)
//   [ITEM_BLOCKS, ITEM_BLOCKS+nG2) : user Gram (64 gathered rows per block)
//   [ITEM_BLOCKS+nG2, ...+B)       : pos_data_loss, one block per batch row
__global__ void __launch_bounds__(TPB)
k_fused(const int* __restrict__ uids,
        const int* __restrict__ pos_iids,
        const float* __restrict__ userW,
        const float* __restrict__ itemW,
        const float* __restrict__ h,
        int B, int L, int PAD, int R, int nG2) {
    __shared__ float sm[64 * DK];       // 16 KB tile / wu scratch
    __shared__ float wsum[TPB / 32];
    const int tid = threadIdx.x;
    const int bid = blockIdx.x;

    if (bid < ITEM_BLOCKS + nG2) {
        // ------------------ Gram path (item or user) ------------------
        const bool isItem = bid < ITEM_BLOCKS;
        int ti = 0, tj = 0;
        const bool active = tid < 136;
        if (active) {                       // upper-tri tile map
            int k = tid, t = 0;
            while (k >= 16 - t) { k -= 16 - t; t++; }
            ti = t; tj = t + k;
        }
        float acc[4][4];
#pragma unroll
        for (int a = 0; a < 4; a++)
#pragma unroll
            for (int b = 0; b < 4; b++) acc[a][b] = 0.f;

        if (isItem) {
            const int n_tiles = (R + 63) / 64;
            for (int t = bid; t < n_tiles; t += ITEM_BLOCKS) {
                const int row0  = t * 64;
                const int valid = min(64, R - row0);
                __syncthreads();
                const float4* src = (const float4*)(itemW + (size_t)row0 * DK);
                float4* dst = (float4*)sm;
                for (int i = tid; i < valid * (DK / 4); i += TPB) dst[i] = src[i];
                __syncthreads();
                if (active) {
                    if (valid == 64) {
#pragma unroll 4
                        for (int r = 0; r < 64; r++) {
                            float4 vi = *(const float4*)&sm[r * DK + ti * 4];
                            float4 vj = *(const float4*)&sm[r * DK + tj * 4];
                            float ai[4] = {vi.x, vi.y, vi.z, vi.w};
                            float aj[4] = {vj.x, vj.y, vj.z, vj.w};
#pragma unroll
                            for (int a = 0; a < 4; a++)
#pragma unroll
                                for (int b = 0; b < 4; b++) acc[a][b] += ai[a] * aj[b];
                        }
                    } else {
                        for (int r = 0; r < valid; r++) {
                            float4 vi = *(const float4*)&sm[r * DK + ti * 4];
                            float4 vj = *(const float4*)&sm[r * DK + tj * 4];
                            float ai[4] = {vi.x, vi.y, vi.z, vi.w};
                            float aj[4] = {vj.x, vj.y, vj.z, vj.w};
#pragma unroll
                            for (int a = 0; a < 4; a++)
#pragma unroll
                                for (int b = 0; b < 4; b++) acc[a][b] += ai[a] * aj[b];
                        }
                    }
                }
            }
        } else {
            const int base = (bid - ITEM_BLOCKS) * 64;
            for (int i = tid; i < 64 * DK; i += TPB) {
                int u = base + (i >> 6);
                sm[i] = (u < B) ? userW[(size_t)uids[u] * DK + (i & 63)] : 0.f;
            }
            __syncthreads();
            if (active) {
#pragma unroll 4
                for (int r = 0; r < 64; r++) {
                    float4 vi = *(const float4*)&sm[r * DK + ti * 4];
                    float4 vj = *(const float4*)&sm[r * DK + tj * 4];
                    float ai[4] = {vi.x, vi.y, vi.z, vi.w};
                    float aj[4] = {vj.x, vj.y, vj.z, vj.w};
#pragma unroll
                    for (int a = 0; a < 4; a++)
#pragma unroll
                        for (int b = 0; b < 4; b++) acc[a][b] += ai[a] * aj[b];
                }
            }
        }
        if (active) {
            float* G = isItem ? g_G1 : g_G2;
#pragma unroll
            for (int a = 0; a < 4; a++)
#pragma unroll
                for (int b = 0; b < 4; b++)
                    atomicAdd(&G[(ti * 4 + a) * DK + tj * 4 + b], acc[a][b]);
            if (ti != tj) {
#pragma unroll
                for (int a = 0; a < 4; a++)
#pragma unroll
                    for (int b = 0; b < 4; b++)
                        atomicAdd(&G[(tj * 4 + b) * DK + ti * 4 + a], acc[a][b]);
            }
        }
    } else {
        // ------------------ hpq: one block per batch row b ------------------
        const int b    = bid - ITEM_BLOCKS - nG2;
        const int lane = tid & 31, w = tid >> 5;
        const int sub  = lane & 7, grp = lane >> 3;

        // wu = userW[uids[b]] * h, computed in-block
        if (tid < DK / 4) {
            float4 hu = ((const float4*)h)[tid];
            float4 uu = ((const float4*)(userW + (size_t)uids[b] * DK))[tid];
            float4 r;
            r.x = hu.x * uu.x; r.y = hu.y * uu.y;
            r.z = hu.z * uu.z; r.w = hu.w * uu.w;
            ((float4*)sm)[tid] = r;
        }
        __syncthreads();

        const float4 w0 = ((const float4*)sm)[sub];        // bytes [0,128)
        const float4 w1 = ((const float4*)sm)[sub + 8];    // bytes [128,256)
        const int* ids = pos_iids + (size_t)b * L;

        float loss = 0.f;
        const int per_step = (TPB / 32) * 16;              // 80 items/step
        const int nsteps = (L + per_step - 1) / per_step;  // 3 for L=200
        for (int s = 0; s < nsteps; s++) {
            const int l0 = s * per_step + (w * 4 + grp) * 4;
            int4 ii;
            if (l0 + 3 < L) {
                ii = *(const int4*)&ids[l0];               // 16B-aligned
            } else {
                ii.x = (l0     < L) ? ids[l0]     : PAD;
                ii.y = (l0 + 1 < L) ? ids[l0 + 1] : PAD;
                ii.z = (l0 + 2 < L) ? ids[l0 + 2] : PAD;
                ii.w = (l0 + 3 < L) ? ids[l0 + 3] : PAD;
            }
            const int iid[4] = {ii.x, ii.y, ii.z, ii.w};
            float4 va[4], vb[4];
#pragma unroll
            for (int t = 0; t < 4; t++) {
                const float4* row = (const float4*)(itemW + (size_t)iid[t] * DK);
                va[t] = row[sub];
                vb[t] = row[sub + 8];
            }
            float d[4];
#pragma unroll
            for (int t = 0; t < 4; t++)
                d[t] = va[t].x * w0.x + va[t].y * w0.y + va[t].z * w0.z + va[t].w * w0.w
                     + vb[t].x * w1.x + vb[t].y * w1.y + vb[t].z * w1.z + vb[t].w * w1.w;
#pragma unroll
            for (int off = 4; off; off >>= 1)
#pragma unroll
                for (int t = 0; t < 4; t++)
                    d[t] += __shfl_xor_sync(0xffffffffu, d[t], off);
            if (sub == 0) {
#pragma unroll
                for (int t = 0; t < 4; t++)
                    if (l0 + t < L && iid[t] != PAD)
                        loss += 0.9f * d[t] * d[t] - 2.0f * d[t];
            }
        }
#pragma unroll
        for (int off = 16; off; off >>= 1)
            loss += __shfl_xor_sync(0xffffffffu, loss, off);
        if (lane == 0) wsum[w] = loss;
        __syncthreads();
        if (tid == 0) {
            float s = 0.f;
#pragma unroll
            for (int k = 0; k < TPB / 32; k++) s += wsum[k];
            g_posp[b] = s;                                 // no atomic
        }
    }
}

// ---------------------------------------------------------------------------
// Final combine (float; 4 independent accumulators; FULL 4096-elem coverage).
__global__ void k_combine(const float* __restrict__ h, float* __restrict__ out,
                          int B) {
    __shared__ float red[256];
    const int tid = threadIdx.x;

    // 0.1 * sum(G1 .* G2 .* h h^T) over all DK*DK = 4096 elements:
    // outer stride 1024, inner offsets {0,256,512,768} -> e covers tid+256*k
    // for k = 0..15 exactly once.
    float a0 = 0.f, a1 = 0.f, a2 = 0.f, a3 = 0.f;
#pragma unroll
    for (int base = 0; base < DK * DK; base += 1024) {
        int e0 = base + tid;
        int e1 = e0 + 256;
        int e2 = e0 + 512;
        int e3 = e0 + 768;
        a0 += g_G1[e0] * g_G2[e0] * h[e0 >> 6] * h[e0 & 63];
        a1 += g_G1[e1] * g_G2[e1] * h[e1 >> 6] * h[e1 & 63];
        a2 += g_G1[e2] * g_G2[e2] * h[e2 >> 6] * h[e2 & 63];
        a3 += g_G1[e3] * g_G2[e3] * h[e3 >> 6] * h[e3 & 63];
    }
    float s = 0.1f * ((a0 + a1) + (a2 + a3));

    // + sum of per-row pos-loss partials
    float b0 = 0.f, b1 = 0.f, b2 = 0.f, b3 = 0.f;
    for (int i = tid; i < B; i += 1024) {
        b0 += g_posp[i];
        if (i + 256 < B) b1 += g_posp[i + 256];
        if (i + 512 < B) b2 += g_posp[i + 512];
        if (i + 768 < B) b3 += g_posp[i + 768];
    }
    s += (b0 + b1) + (b2 + b3);

    red[tid] = s;
    __syncthreads();
    for (int k = 128; k >= 32; k >>= 1) {
        if (tid < k) red[tid] += red[tid + k];
        __syncthreads();
    }
    if (tid < 32) {
        float v = red[tid];
#pragma unroll
        for (int off = 16; off; off >>= 1)
            v += __shfl_xor_sync(0xffffffffu, v, off);
        if (tid == 0) out[0] = v;
    }
}

// ---------------------------------------------------------------------------
extern "C" void kernel_launch(void* const* d_in, const int* in_sizes, int n_in,
                              void* d_out, int out_size) {
    const int*   uids     = (const int*)d_in[0];
    const int*   pos_iids = (const int*)d_in[1];
    const float* user_W   = (const float*)d_in[2];
    const float* item_W   = (const float*)d_in[3];
    const float* h        = (const float*)d_in[4];
    float* out = (float*)d_out;

    const int B   = in_sizes[0];          // 4096
    const int L   = in_sizes[1] / B;      // 200
    const int R   = in_sizes[3] / DK;     // 100001 item rows
    const int PAD = R - 1;                // padding item id
    const int nG2 = (B + 63) / 64;        // user-gram blocks

    void *pG1 = nullptr, *pG2 = nullptr;
    cudaGetSymbolAddress(&pG1, g_G1);
    cudaGetSymbolAddress(&pG2, g_G2);
    cudaMemsetAsync(pG1, 0, DK * DK * sizeof(float));
    cudaMemsetAsync(pG2, 0, DK * DK * sizeof(float));

    k_fused<<<ITEM_BLOCKS + nG2 + B, TPB>>>(uids, pos_iids, user_W, item_W, h,
                                            B, L, PAD, R, nG2);
    k_combine<<<1, 256>>>(h, out, B);
}

// round 16
// speedup vs baseline: 1.6967x; 1.0774x over previous
#include <cuda_runtime.h>
#include <cuda_bf16.h>
#include <cstddef>

#define DK 64
#define TPB 160             // 5 warps
#define ITEM_BLOCKS 444
#define B_MAX 4096

// Scratch (no cudaMalloc allowed)
__device__ float g_G1[DK * DK];     // item_W^T item_W   (atomic)
__device__ float g_G2[DK * DK];     // u_emb^T u_emb     (atomic)
__device__ float g_posp[B_MAX];     // per-row pos-loss partials

// ---------------------------------------------------------------------------
// One kernel, three block roles:
//   [0, ITEM_BLOCKS)               : item Gram (upper-tri 4x4 tiles, 136 thr)
//   [ITEM_BLOCKS, ITEM_BLOCKS+nG2) : user Gram (64 gathered rows per block)
//   [ITEM_BLOCKS+nG2, ...+B)       : pos_data_loss, one block per batch row
__global__ void __launch_bounds__(TPB)
k_fused(const int* __restrict__ uids,
        const int* __restrict__ pos_iids,
        const float* __restrict__ userW,
        const float* __restrict__ itemW,
        const float* __restrict__ h,
        int B, int L, int PAD, int R, int nG2) {
    __shared__ float sm[64 * DK];       // 16 KB tile / wu scratch
    __shared__ float wsum[TPB / 32];
    const int tid = threadIdx.x;
    const int bid = blockIdx.x;

    if (bid < ITEM_BLOCKS + nG2) {
        // ------------------ Gram path (item or user) ------------------
        const bool isItem = bid < ITEM_BLOCKS;
        int ti = 0, tj = 0;
        const bool active = tid < 136;
        if (active) {                       // upper-tri tile map
            int k = tid, t = 0;
            while (k >= 16 - t) { k -= 16 - t; t++; }
            ti = t; tj = t + k;
        }
        float acc[4][4];
#pragma unroll
        for (int a = 0; a < 4; a++)
#pragma unroll
            for (int b = 0; b < 4; b++) acc[a][b] = 0.f;

        if (isItem) {
            const int n_tiles = (R + 63) / 64;
            for (int t = bid; t < n_tiles; t += ITEM_BLOCKS) {
                const int row0  = t * 64;
                const int valid = min(64, R - row0);
                __syncthreads();
                const float4* src = (const float4*)(itemW + (size_t)row0 * DK);
                float4* dst = (float4*)sm;
                for (int i = tid; i < valid * (DK / 4); i += TPB) dst[i] = src[i];
                __syncthreads();
                if (active) {
                    if (valid == 64) {
#pragma unroll 4
                        for (int r = 0; r < 64; r++) {
                            float4 vi = *(const float4*)&sm[r * DK + ti * 4];
                            float4 vj = *(const float4*)&sm[r * DK + tj * 4];
                            float ai[4] = {vi.x, vi.y, vi.z, vi.w};
                            float aj[4] = {vj.x, vj.y, vj.z, vj.w};
#pragma unroll
                            for (int a = 0; a < 4; a++)
#pragma unroll
                                for (int b = 0; b < 4; b++) acc[a][b] += ai[a] * aj[b];
                        }
                    } else {
                        for (int r = 0; r < valid; r++) {
                            float4 vi = *(const float4*)&sm[r * DK + ti * 4];
                            float4 vj = *(const float4*)&sm[r * DK + tj * 4];
                            float ai[4] = {vi.x, vi.y, vi.z, vi.w};
                            float aj[4] = {vj.x, vj.y, vj.z, vj.w};
#pragma unroll
                            for (int a = 0; a < 4; a++)
#pragma unroll
                                for (int b = 0; b < 4; b++) acc[a][b] += ai[a] * aj[b];
                        }
                    }
                }
            }
        } else {
            const int base = (bid - ITEM_BLOCKS) * 64;
            for (int i = tid; i < 64 * DK; i += TPB) {
                int u = base + (i >> 6);
                sm[i] = (u < B) ? userW[(size_t)uids[u] * DK + (i & 63)] : 0.f;
            }
            __syncthreads();
            if (active) {
#pragma unroll 4
                for (int r = 0; r < 64; r++) {
                    float4 vi = *(const float4*)&sm[r * DK + ti * 4];
                    float4 vj = *(const float4*)&sm[r * DK + tj * 4];
                    float ai[4] = {vi.x, vi.y, vi.z, vi.w};
                    float aj[4] = {vj.x, vj.y, vj.z, vj.w};
#pragma unroll
                    for (int a = 0; a < 4; a++)
#pragma unroll
                        for (int b = 0; b < 4; b++) acc[a][b] += ai[a] * aj[b];
                }
            }
        }
        if (active) {
            float* G = isItem ? g_G1 : g_G2;
#pragma unroll
            for (int a = 0; a < 4; a++)
#pragma unroll
                for (int b = 0; b < 4; b++)
                    atomicAdd(&G[(ti * 4 + a) * DK + tj * 4 + b], acc[a][b]);
            if (ti != tj) {
#pragma unroll
                for (int a = 0; a < 4; a++)
#pragma unroll
                    for (int b = 0; b < 4; b++)
                        atomicAdd(&G[(tj * 4 + b) * DK + ti * 4 + a], acc[a][b]);
            }
        }
    } else {
        // ---------- hpq: one block per batch row b (2 items per group) ----------
        const int b    = bid - ITEM_BLOCKS - nG2;
        const int lane = tid & 31, w = tid >> 5;
        const int sub  = lane & 7, grp = lane >> 3;

        // wu = userW[uids[b]] * h, computed in-block
        if (tid < DK / 4) {
            float4 hu = ((const float4*)h)[tid];
            float4 uu = ((const float4*)(userW + (size_t)uids[b] * DK))[tid];
            float4 r;
            r.x = hu.x * uu.x; r.y = hu.y * uu.y;
            r.z = hu.z * uu.z; r.w = hu.w * uu.w;
            ((float4*)sm)[tid] = r;
        }
        __syncthreads();

        const float4 w0 = ((const float4*)sm)[sub];        // bytes [0,128)
        const float4 w1 = ((const float4*)sm)[sub + 8];    // bytes [128,256)
        const int* ids = pos_iids + (size_t)b * L;

        float loss = 0.f;
        const int per_step = (TPB / 32) * 8;               // 40 items/step
        const int nsteps = (L + per_step - 1) / per_step;  // 5 for L=200
        for (int s = 0; s < nsteps; s++) {
            const int l1 = s * per_step + w * 8 + grp * 2;
            const int l2 = l1 + 1;
            const int i1 = (l1 < L) ? ids[l1] : PAD;       // PAD row is valid mem
            const int i2 = (l2 < L) ? ids[l2] : PAD;
            const float4* r1 = (const float4*)(itemW + (size_t)i1 * DK);
            const float4* r2 = (const float4*)(itemW + (size_t)i2 * DK);
            float4 a0 = r1[sub], a1 = r1[sub + 8];          // 4 indep LDG.128
            float4 b0 = r2[sub], b1 = r2[sub + 8];
            float d1 = a0.x * w0.x + a0.y * w0.y + a0.z * w0.z + a0.w * w0.w
                     + a1.x * w1.x + a1.y * w1.y + a1.z * w1.z + a1.w * w1.w;
            float d2 = b0.x * w0.x + b0.y * w0.y + b0.z * w0.z + b0.w * w0.w
                     + b1.x * w1.x + b1.y * w1.y + b1.z * w1.z + b1.w * w1.w;
            d1 += __shfl_xor_sync(0xffffffffu, d1, 4);
            d2 += __shfl_xor_sync(0xffffffffu, d2, 4);
            d1 += __shfl_xor_sync(0xffffffffu, d1, 2);
            d2 += __shfl_xor_sync(0xffffffffu, d2, 2);
            d1 += __shfl_xor_sync(0xffffffffu, d1, 1);
            d2 += __shfl_xor_sync(0xffffffffu, d2, 1);
            if (sub == 0) {
                if (l1 < L && i1 != PAD) loss += 0.9f * d1 * d1 - 2.0f * d1;
                if (l2 < L && i2 != PAD) loss += 0.9f * d2 * d2 - 2.0f * d2;
            }
        }
#pragma unroll
        for (int off = 16; off; off >>= 1)
            loss += __shfl_xor_sync(0xffffffffu, loss, off);
        if (lane == 0) wsum[w] = loss;
        __syncthreads();
        if (tid == 0) {
            float s = 0.f;
#pragma unroll
            for (int k = 0; k < TPB / 32; k++) s += wsum[k];
            g_posp[b] = s;                                 // no atomic
        }
    }
}

// ---------------------------------------------------------------------------
// Final combine (float; 512 threads; full 4096-elem coverage).
__global__ void k_combine(const float* __restrict__ h, float* __restrict__ out,
                          int B) {
    __shared__ float red[512];
    const int tid = threadIdx.x;

    // 0.1 * sum(G1 .* G2 .* h h^T) over DK*DK = 4096 elements.
    float a0 = 0.f, a1 = 0.f, a2 = 0.f, a3 = 0.f;
#pragma unroll
    for (int base = 0; base < DK * DK; base += 2048) {
        int e0 = base + tid;
        int e1 = e0 + 512;
        int e2 = e0 + 1024;
        int e3 = e0 + 1536;
        a0 += g_G1[e0] * g_G2[e0] * h[e0 >> 6] * h[e0 & 63];
        a1 += g_G1[e1] * g_G2[e1] * h[e1 >> 6] * h[e1 & 63];
        a2 += g_G1[e2] * g_G2[e2] * h[e2 >> 6] * h[e2 & 63];
        a3 += g_G1[e3] * g_G2[e3] * h[e3 >> 6] * h[e3 & 63];
    }
    float s = 0.1f * ((a0 + a1) + (a2 + a3));

    // + sum of per-row pos-loss partials
    float b0 = 0.f, b1 = 0.f, b2 = 0.f, b3 = 0.f;
    for (int i = tid; i < B; i += 2048) {
        b0 += g_posp[i];
        if (i + 512  < B) b1 += g_posp[i + 512];
        if (i + 1024 < B) b2 += g_posp[i + 1024];
        if (i + 1536 < B) b3 += g_posp[i + 1536];
    }
    s += (b0 + b1) + (b2 + b3);

    red[tid] = s;
    __syncthreads();
    for (int k = 256; k >= 32; k >>= 1) {
        if (tid < k) red[tid] += red[tid + k];
        __syncthreads();
    }
    if (tid < 32) {
        float v = red[tid];
#pragma unroll
        for (int off = 16; off; off >>= 1)
            v += __shfl_xor_sync(0xffffffffu, v, off);
        if (tid == 0) out[0] = v;
    }
}

// ---------------------------------------------------------------------------
extern "C" void kernel_launch(void* const* d_in, const int* in_sizes, int n_in,
                              void* d_out, int out_size) {
    const int*   uids     = (const int*)d_in[0];
    const int*   pos_iids = (const int*)d_in[1];
    const float* user_W   = (const float*)d_in[2];
    const float* item_W   = (const float*)d_in[3];
    const float* h        = (const float*)d_in[4];
    float* out = (float*)d_out;

    const int B   = in_sizes[0];          // 4096
    const int L   = in_sizes[1] / B;      // 200
    const int R   = in_sizes[3] / DK;     // 100001 item rows
    const int PAD = R - 1;                // padding item id
    const int nG2 = (B + 63) / 64;        // user-gram blocks

    void *pG1 = nullptr, *pG2 = nullptr;
    cudaGetSymbolAddress(&pG1, g_G1);
    cudaGetSymbolAddress(&pG2, g_G2);
    cudaMemsetAsync(pG1, 0, DK * DK * sizeof(float));
    cudaMemsetAsync(pG2, 0, DK * DK * sizeof(float));

    k_fused<<<ITEM_BLOCKS + nG2 + B, TPB>>>(uids, pos_iids, user_W, item_W, h,
                                            B, L, PAD, R, nG2);
    k_combine<<<1, 512>>>(h, out, B);
}